// round 12
// baseline (speedup 1.0000x reference)
#include <cuda_runtime.h>
#include <cuda_fp16.h>
#include <cuda_bf16.h>

#define BATCH 4
#define N 4096
#define RN (BATCH * N)
#define EPS 1e-6f
#define NITER 20

// fused kernel geometry: block = 8 rows x 4096 cols, 2 groups of 4 rows
#define RPG 4                    // rows per group (register-resident)
#define GROUPS 2
#define RPS (RPG * GROUPS)       // 8 rows per block
#define SPBATCH (N / RPS)        // 512 strips per batch
#define GRID_F (BATCH * SPBATCH) // 2048 fused blocks

// Device-global scratch
__device__ unsigned short g_E[(size_t)BATCH * N * N];   // 128 MB bf16 exp(x-rowmax)
__device__ float  g_r[RN];
__device__ float  g_c[RN];
__device__ float  g_rowmax[RN];
__device__ __half g_vpart[(size_t)GRID_F * N];          // 16 MB fp16 col partials

// exact bf16x2 -> float2 (bit surgery, ALU pipe)
__device__ __forceinline__ float2 bf2f(unsigned u) {
    float2 f;
    f.x = __int_as_float(u << 16);
    f.y = __int_as_float(u & 0xffff0000u);
    return f;
}

__device__ __forceinline__ float warpSum(float v) {
    #pragma unroll
    for (int o = 16; o > 0; o >>= 1) v += __shfl_xor_sync(0xffffffffu, v, o);
    return v;
}
__device__ __forceinline__ float warpMax(float v) {
    #pragma unroll
    for (int o = 16; o > 0; o >>= 1) v = fmaxf(v, __shfl_xor_sync(0xffffffffu, v, o));
    return v;
}

// ---------------------------------------------------------------------------
// prep: rowmax, E = bf16 exp(x - max), fold FIRST row step (c=1):
//   r_i = 1/(rowsum(bf16-rounded) + eps);  c_j = 1
// ---------------------------------------------------------------------------
__global__ __launch_bounds__(256) void prep_kernel(const float* __restrict__ logits) {
    const int row = blockIdx.x;
    const int t   = threadIdx.x;
    const float4* src = (const float4*)(logits + (size_t)row * N);

    float4 vals[4];
    #pragma unroll
    for (int k = 0; k < 4; ++k) vals[k] = src[t + k * 256];

    float m = -__int_as_float(0x7f800000);
    #pragma unroll
    for (int k = 0; k < 4; ++k)
        m = fmaxf(m, fmaxf(fmaxf(vals[k].x, vals[k].y), fmaxf(vals[k].z, vals[k].w)));

    __shared__ float sh[32];
    __shared__ float s_bc;
    const int lane = t & 31, w = t >> 5;
    float wm = warpMax(m);
    if (lane == 0) sh[w] = wm;
    __syncthreads();
    if (w == 0) {
        float v = (lane < 8) ? sh[lane] : -__int_as_float(0x7f800000);
        v = warpMax(v);
        if (lane == 0) s_bc = v;
    }
    __syncthreads();
    const float mx = s_bc;
    __syncthreads();

    unsigned* dst = (unsigned*)(g_E + (size_t)row * N);   // bf16x2 words
    float sum = 0.0f;
    #pragma unroll
    for (int k = 0; k < 4; ++k) {
        const float4 v = vals[k];
        const int i4 = t + k * 256;
        __nv_bfloat162 b0 = __floats2bfloat162_rn(__expf(v.x - mx), __expf(v.y - mx));
        __nv_bfloat162 b1 = __floats2bfloat162_rn(__expf(v.z - mx), __expf(v.w - mx));
        const unsigned u0 = *(unsigned*)&b0;
        const unsigned u1 = *(unsigned*)&b1;
        dst[2 * i4 + 0] = u0;
        dst[2 * i4 + 1] = u1;
        const float2 f0 = bf2f(u0), f1 = bf2f(u1);
        sum += (f0.x + f0.y) + (f1.x + f1.y);
    }
    float ws = warpSum(sum);
    if (lane == 0) sh[w] = ws;
    __syncthreads();
    if (t == 0) {
        float u = 0.0f;
        #pragma unroll
        for (int i = 0; i < 8; ++i) u += sh[i];
        g_rowmax[row] = mx;
        g_r[row] = 1.0f / (u + EPS);
        g_c[row] = 1.0f;
    }
}

// ---------------------------------------------------------------------------
// fused iteration: 256-thread blocks, 8 rows x 4096 cols, 2 groups of 4 rows.
// Thread t owns uint4 slices t and t+256 of each row (cols [8t,8t+8) and
// [2048+8t, 2048+8t+8)). 4 CTAs/SM; 8-warp barriers; one E read per iter.
// ---------------------------------------------------------------------------
__global__ __launch_bounds__(256, 4) void fused_kernel(int do_row) {
    __shared__ float s_u[2][RPG * 8];    // [parity][row*8 + warp]
    __shared__ float r_s[2][RPG];

    const int bid   = blockIdx.x;
    const int b     = bid >> 9;              // batch (512 strips per batch)
    const int strip = bid & (SPBATCH - 1);
    const int t     = threadIdx.x;
    const int w     = t >> 5, lane = t & 31;
    const int row0  = strip * RPS;           // within batch

    const uint4* Eb = (const uint4*)(g_E + (size_t)b * N * N);  // 512 uint4/row

    // prefetch r for my row (threads 0..7 own the strip's 8 rows)
    float r_pre = 0.0f;
    if (t < RPS) r_pre = g_r[b * N + row0 + t];

    // my 16 c values: cols [8t,8t+8) and [2048+8t,2048+8t+8)
    const float4* cb = (const float4*)(g_c + b * N);
    const float4 cA = cb[2 * t];
    const float4 cB = cb[2 * t + 1];
    const float4 cC = cb[512 + 2 * t];
    const float4 cD = cb[512 + 2 * t + 1];

    float a0 = 0.f, a1 = 0.f, a2 = 0.f, a3 = 0.f;
    float a4 = 0.f, a5 = 0.f, a6 = 0.f, a7 = 0.f;
    float b0 = 0.f, b1 = 0.f, b2 = 0.f, b3 = 0.f;
    float b4 = 0.f, b5 = 0.f, b6 = 0.f, b7 = 0.f;

    #pragma unroll
    for (int grp = 0; grp < GROUPS; ++grp) {
        const int p    = grp & 1;
        const int rowg = row0 + grp * RPG;
        const uint4* Es = Eb + (size_t)rowg * 512 + t;

        uint4 eL[RPG], eR[RPG];
        #pragma unroll
        for (int i = 0; i < RPG; ++i) {
            eL[i] = Es[(size_t)i * 512];
            eR[i] = Es[(size_t)i * 512 + 256];
        }

        if (do_row) {
            float v[RPG];
            #pragma unroll
            for (int i = 0; i < RPG; ++i) {
                const float2 f0 = bf2f(eL[i].x), f1 = bf2f(eL[i].y);
                const float2 f2 = bf2f(eL[i].z), f3 = bf2f(eL[i].w);
                const float2 g0 = bf2f(eR[i].x), g1 = bf2f(eR[i].y);
                const float2 g2 = bf2f(eR[i].z), g3 = bf2f(eR[i].w);
                float aa = 0.f, bb = 0.f;
                aa = fmaf(f0.x, cA.x, aa); aa = fmaf(f0.y, cA.y, aa);
                aa = fmaf(f1.x, cA.z, aa); aa = fmaf(f1.y, cA.w, aa);
                aa = fmaf(f2.x, cB.x, aa); aa = fmaf(f2.y, cB.y, aa);
                aa = fmaf(f3.x, cB.z, aa); aa = fmaf(f3.y, cB.w, aa);
                bb = fmaf(g0.x, cC.x, bb); bb = fmaf(g0.y, cC.y, bb);
                bb = fmaf(g1.x, cC.z, bb); bb = fmaf(g1.y, cC.w, bb);
                bb = fmaf(g2.x, cD.x, bb); bb = fmaf(g2.y, cD.y, bb);
                bb = fmaf(g3.x, cD.z, bb); bb = fmaf(g3.y, cD.w, bb);
                v[i] = aa + bb;
            }
            // fold reduction over 4 values: 8 shfl; row k ends at lanes 8k
            {
                float ta = __shfl_xor_sync(0xffffffffu, v[0], 16);
                float tb = __shfl_xor_sync(0xffffffffu, v[2], 16);
                v[0] = (lane < 16) ? (v[0] + ta) : (v[2] + tb);
                ta = __shfl_xor_sync(0xffffffffu, v[1], 16);
                tb = __shfl_xor_sync(0xffffffffu, v[3], 16);
                v[1] = (lane < 16) ? (v[1] + ta) : (v[3] + tb);
                ta = __shfl_xor_sync(0xffffffffu, v[0], 8);
                tb = __shfl_xor_sync(0xffffffffu, v[1], 8);
                v[0] = ((lane & 8) == 0) ? (v[0] + ta) : (v[1] + tb);
                v[0] += __shfl_xor_sync(0xffffffffu, v[0], 4);
                v[0] += __shfl_xor_sync(0xffffffffu, v[0], 2);
                v[0] += __shfl_xor_sync(0xffffffffu, v[0], 1);
            }
            if ((lane & 7) == 0) s_u[p][(lane >> 3) * 8 + w] = v[0];
            __syncthreads();
            // threads grp*4..grp*4+3 own this group's rows (their r_pre)
            if ((t >> 2) == grp) {
                const int i = t & 3;
                float u = 0.f;
                #pragma unroll
                for (int w2 = 0; w2 < 8; ++w2) u += s_u[p][i * 8 + w2];
                const float rn = r_pre / fmaf(r_pre, u, EPS);
                g_r[b * N + rowg + i] = rn;   // fire-and-forget store
                r_s[p][i] = rn;
            }
        } else {
            if ((t >> 2) == grp) r_s[p][t & 3] = r_pre;
        }
        __syncthreads();

        // phase B: thread-local column sums over register-held rows
        #pragma unroll
        for (int i = 0; i < RPG; ++i) {
            const float ri = r_s[p][i];
            const float2 f0 = bf2f(eL[i].x), f1 = bf2f(eL[i].y);
            const float2 f2 = bf2f(eL[i].z), f3 = bf2f(eL[i].w);
            const float2 g0 = bf2f(eR[i].x), g1 = bf2f(eR[i].y);
            const float2 g2 = bf2f(eR[i].z), g3 = bf2f(eR[i].w);
            a0 = fmaf(f0.x, ri, a0); a1 = fmaf(f0.y, ri, a1);
            a2 = fmaf(f1.x, ri, a2); a3 = fmaf(f1.y, ri, a3);
            a4 = fmaf(f2.x, ri, a4); a5 = fmaf(f2.y, ri, a5);
            a6 = fmaf(f3.x, ri, a6); a7 = fmaf(f3.y, ri, a7);
            b0 = fmaf(g0.x, ri, b0); b1 = fmaf(g0.y, ri, b1);
            b2 = fmaf(g1.x, ri, b2); b3 = fmaf(g1.y, ri, b3);
            b4 = fmaf(g2.x, ri, b4); b5 = fmaf(g2.y, ri, b5);
            b6 = fmaf(g3.x, ri, b6); b7 = fmaf(g3.y, ri, b7);
        }
        // no trailing barrier: next group uses the other parity buffers
    }

    // pack 16 fp32 partials -> 16 fp16, two STG.128
    __half2 h0 = __floats2half2_rn(a0, a1), h1 = __floats2half2_rn(a2, a3);
    __half2 h2 = __floats2half2_rn(a4, a5), h3 = __floats2half2_rn(a6, a7);
    __half2 k0 = __floats2half2_rn(b0, b1), k1 = __floats2half2_rn(b2, b3);
    __half2 k2 = __floats2half2_rn(b4, b5), k3 = __floats2half2_rn(b6, b7);
    uint4 pa, pb;
    pa.x = *(unsigned*)&h0; pa.y = *(unsigned*)&h1;
    pa.z = *(unsigned*)&h2; pa.w = *(unsigned*)&h3;
    pb.x = *(unsigned*)&k0; pb.y = *(unsigned*)&k1;
    pb.z = *(unsigned*)&k2; pb.w = *(unsigned*)&k3;
    uint4* vp = (uint4*)(g_vpart + (size_t)bid * N);
    vp[t]       = pa;
    vp[t + 256] = pb;
}

// ---------------------------------------------------------------------------
// finalize: quad of threads per half2 column-pair; each sums 128 fp16
// partials in fixed order (fp32 accum), fixed-order shfl combine; 2 c updates.
// ---------------------------------------------------------------------------
__global__ __launch_bounds__(256) void col_finalize() {
    const int tt   = threadIdx.x;
    const int pair = blockIdx.x * 64 + (tt >> 2);  // global half2 index, 0..8191
    const int q    = tt & 3;
    const int b    = pair >> 11;                   // 2048 half2 per batch
    const int jp   = pair & 2047;

    const __half2* vp = (const __half2*)g_vpart
                      + (size_t)(b * SPBATCH + q * 128) * (N / 2) + jp;
    float vx = 0.f, vy = 0.f;
    #pragma unroll 8
    for (int s = 0; s < 128; ++s) {
        const float2 f = __half22float2(vp[(size_t)s * (N / 2)]);
        vx += f.x; vy += f.y;
    }
    vx += __shfl_down_sync(0xffffffffu, vx, 1);
    vy += __shfl_down_sync(0xffffffffu, vy, 1);
    vx += __shfl_down_sync(0xffffffffu, vx, 2);
    vy += __shfl_down_sync(0xffffffffu, vy, 2);
    if (q == 0) {
        const int col = pair * 2;          // global (b*N + j)
        const float c0 = g_c[col];
        const float c1 = g_c[col + 1];
        g_c[col]     = c0 / fmaf(c0, vx, EPS);
        g_c[col + 1] = c1 / fmaf(c1, vy, EPS);
    }
}

// ---------------------------------------------------------------------------
// output: out_ij = exp(x_ij - rowmax_i) * r_i * c_j (fp32 path)
// ---------------------------------------------------------------------------
__global__ __launch_bounds__(256) void out_kernel(const float* __restrict__ logits,
                                                  float* __restrict__ out) {
    const size_t g  = (size_t)blockIdx.x * 256 + threadIdx.x;  // float4 index
    const size_t e0 = g * 4;
    const int row = (int)(e0 >> 12);
    const int b   = row >> 12;
    const int j   = (int)(e0 & (N - 1));

    const float mx = g_rowmax[row];
    const float r  = g_r[row];
    const float4 x = ((const float4*)logits)[g];
    const float4 c = *(const float4*)(g_c + b * N + j);

    float4 o;
    o.x = __expf(x.x - mx) * r * c.x;
    o.y = __expf(x.y - mx) * r * c.y;
    o.z = __expf(x.z - mx) * r * c.z;
    o.w = __expf(x.w - mx) * r * c.w;
    ((float4*)out)[g] = o;
}

extern "C" void kernel_launch(void* const* d_in, const int* in_sizes, int n_in,
                              void* d_out, int out_size) {
    const float* logits = (const float*)d_in[0];
    float* out = (float*)d_out;

    prep_kernel<<<RN, 256>>>(logits);          // includes row step #1
    for (int it = 0; it < NITER; ++it) {
        fused_kernel<<<GRID_F, 256>>>(it > 0); // it=0: col only (row folded)
        col_finalize<<<RN / 128, 256>>>();
    }
    out_kernel<<<(int)(((size_t)BATCH * N * N / 4) / 256), 256>>>(logits, out);
}

// round 14
// speedup vs baseline: 1.3691x; 1.3691x over previous
#include <cuda_runtime.h>
#include <cuda_fp16.h>
#include <cuda_bf16.h>

#define BATCH 4
#define N 4096
#define RN (BATCH * N)
#define EPS 1e-6f
#define NITER 20

#define RPG 8                    // rows per group (register-resident)
#define GROUPS 2                 // groups per block -> 16 rows per block
#define RPS (RPG * GROUPS)
#define SPBATCH (N / RPS)        // 256 strips per batch
#define GRID_F (BATCH * SPBATCH) // 1024 fused blocks

typedef unsigned long long u64;

// Device-global scratch
__device__ unsigned short g_E[(size_t)BATCH * N * N];  // 128 MB bf16 exp(x-rowmax)
__device__ float  g_r[RN];
__device__ float  g_c[RN];
__device__ float  g_rowmax[RN];
__device__ __half g_vpart[(size_t)GRID_F * N];         // 8 MB fp16 col partials

// ---- L2 cache-policy helpers (createpolicy + cache_hint; v4.u32-legal) ----
__device__ __forceinline__ u64 policy_evict_last() {
    u64 p;
    asm("createpolicy.fractional.L2::evict_last.b64 %0, 1.0;" : "=l"(p));
    return p;
}
__device__ __forceinline__ u64 policy_evict_first() {
    u64 p;
    asm("createpolicy.fractional.L2::evict_first.b64 %0, 1.0;" : "=l"(p));
    return p;
}
__device__ __forceinline__ uint4 ldg_pol(const uint4* p, u64 pol) {
    uint4 v;
    asm volatile("ld.global.L2::cache_hint.v4.u32 {%0,%1,%2,%3}, [%4], %5;"
                 : "=r"(v.x), "=r"(v.y), "=r"(v.z), "=r"(v.w)
                 : "l"(p), "l"(pol));
    return v;
}
__device__ __forceinline__ void stg_pol2(unsigned* p, unsigned a, unsigned b, u64 pol) {
    asm volatile("st.global.L2::cache_hint.v2.u32 [%0], {%1,%2}, %3;"
                 :: "l"(p), "r"(a), "r"(b), "l"(pol) : "memory");
}
__device__ __forceinline__ void stg_pol4(uint4* p, uint4 v, u64 pol) {
    asm volatile("st.global.L2::cache_hint.v4.u32 [%0], {%1,%2,%3,%4}, %5;"
                 :: "l"(p), "r"(v.x), "r"(v.y), "r"(v.z), "r"(v.w), "l"(pol)
                 : "memory");
}

// exact bf16x2 -> float2 (bit surgery, ALU pipe)
__device__ __forceinline__ float2 bf2f(unsigned u) {
    float2 f;
    f.x = __int_as_float(u << 16);
    f.y = __int_as_float(u & 0xffff0000u);
    return f;
}

__device__ __forceinline__ float warpSum(float v) {
    #pragma unroll
    for (int o = 16; o > 0; o >>= 1) v += __shfl_xor_sync(0xffffffffu, v, o);
    return v;
}
__device__ __forceinline__ float warpMax(float v) {
    #pragma unroll
    for (int o = 16; o > 0; o >>= 1) v = fmaxf(v, __shfl_xor_sync(0xffffffffu, v, o));
    return v;
}

// ---------------------------------------------------------------------------
// prep: rowmax, E = bf16 exp(x - max), fold FIRST row step (c=1):
//   r_i = 1/(rowsum(bf16-rounded) + eps);  c_j = 1
// E stores hinted: batches 0-1 evict_last (L2-pinned), 2-3 evict_first.
// ---------------------------------------------------------------------------
__global__ __launch_bounds__(256) void prep_kernel(const float* __restrict__ logits) {
    const int row = blockIdx.x;
    const int t   = threadIdx.x;
    const u64 pol = ((row >> 12) < 2) ? policy_evict_last() : policy_evict_first();
    const float4* src = (const float4*)(logits + (size_t)row * N);

    float4 vals[4];
    #pragma unroll
    for (int k = 0; k < 4; ++k) vals[k] = src[t + k * 256];

    float m = -__int_as_float(0x7f800000);
    #pragma unroll
    for (int k = 0; k < 4; ++k)
        m = fmaxf(m, fmaxf(fmaxf(vals[k].x, vals[k].y), fmaxf(vals[k].z, vals[k].w)));

    __shared__ float sh[32];
    __shared__ float s_bc;
    const int lane = t & 31, w = t >> 5;
    float wm = warpMax(m);
    if (lane == 0) sh[w] = wm;
    __syncthreads();
    if (w == 0) {
        float v = (lane < 8) ? sh[lane] : -__int_as_float(0x7f800000);
        v = warpMax(v);
        if (lane == 0) s_bc = v;
    }
    __syncthreads();
    const float mx = s_bc;
    __syncthreads();

    unsigned* dst = (unsigned*)(g_E + (size_t)row * N);   // bf16x2 words
    float sum = 0.0f;
    #pragma unroll
    for (int k = 0; k < 4; ++k) {
        const float4 v = vals[k];
        const int i4 = t + k * 256;
        __nv_bfloat162 b0 = __floats2bfloat162_rn(__expf(v.x - mx), __expf(v.y - mx));
        __nv_bfloat162 b1 = __floats2bfloat162_rn(__expf(v.z - mx), __expf(v.w - mx));
        const unsigned u0 = *(unsigned*)&b0;
        const unsigned u1 = *(unsigned*)&b1;
        stg_pol2(dst + 2 * i4, u0, u1, pol);
        const float2 f0 = bf2f(u0), f1 = bf2f(u1);
        sum += (f0.x + f0.y) + (f1.x + f1.y);
    }
    float ws = warpSum(sum);
    if (lane == 0) sh[w] = ws;
    __syncthreads();
    if (t == 0) {
        float u = 0.0f;
        #pragma unroll
        for (int i = 0; i < 8; ++i) u += sh[i];
        g_rowmax[row] = mx;
        g_r[row] = 1.0f / (u + EPS);
        g_c[row] = 1.0f;
    }
}

// ---------------------------------------------------------------------------
// fused iteration (R10 structure): ONE read of E, 8-row register groups,
// bf16 bit-surgery, r prefetched, fold reduction, fp16 partial STG.128.
// E loads hinted: batches 0-1 evict_last, batches 2-3 evict_first.
// ---------------------------------------------------------------------------
__global__ __launch_bounds__(512, 2) void fused_kernel(int do_row) {
    __shared__ float s_u[2][RPG * 16];   // [parity][row*16 + warp]
    __shared__ float r_s[2][RPG];

    const int bid   = blockIdx.x;
    const int b     = bid >> 8;              // batch
    const int strip = bid & (SPBATCH - 1);
    const int t     = threadIdx.x;
    const int w     = t >> 5, lane = t & 31;
    const int row0  = strip * RPS;           // within batch

    const u64 polE = (b < 2) ? policy_evict_last() : policy_evict_first();
    const u64 polS = policy_evict_first();

    const uint4* Eb = (const uint4*)(g_E + (size_t)b * N * N);  // 512 uint4/row

    // prefetch r for my row (threads 0..15 own the strip's 16 rows)
    float r_pre = 0.0f;
    if (t < RPS) r_pre = g_r[b * N + row0 + t];

    // my 8 c values (columns [8t, 8t+8))
    const float4* cb = (const float4*)(g_c + b * N);
    const float4 cA = cb[2 * t];
    const float4 cB = cb[2 * t + 1];

    float a0 = 0.f, a1 = 0.f, a2 = 0.f, a3 = 0.f;
    float a4 = 0.f, a5 = 0.f, a6 = 0.f, a7 = 0.f;

    #pragma unroll
    for (int grp = 0; grp < GROUPS; ++grp) {
        const int p    = grp & 1;
        const int rowg = row0 + grp * RPG;
        const uint4* Es = Eb + (size_t)rowg * 512 + t;

        uint4 e[RPG];
        #pragma unroll
        for (int i = 0; i < RPG; ++i) e[i] = ldg_pol(Es + (size_t)i * 512, polE);

        if (do_row) {
            float v[RPG];
            #pragma unroll
            for (int i = 0; i < RPG; ++i) {
                const float2 f0 = bf2f(e[i].x);
                const float2 f1 = bf2f(e[i].y);
                const float2 f2 = bf2f(e[i].z);
                const float2 f3 = bf2f(e[i].w);
                float a = 0.f;
                a = fmaf(f0.x, cA.x, a); a = fmaf(f0.y, cA.y, a);
                a = fmaf(f1.x, cA.z, a); a = fmaf(f1.y, cA.w, a);
                a = fmaf(f2.x, cB.x, a); a = fmaf(f2.y, cB.y, a);
                a = fmaf(f3.x, cB.z, a); a = fmaf(f3.y, cB.w, a);
                v[i] = a;
            }
            // fold reduction: 16 shfl + 16 add; row k ends at lanes (k<<2)
            #pragma unroll
            for (int i = 0; i < 4; ++i) {
                const float ta = __shfl_xor_sync(0xffffffffu, v[i], 16);
                const float tb = __shfl_xor_sync(0xffffffffu, v[i + 4], 16);
                v[i] = (lane < 16) ? (v[i] + ta) : (v[i + 4] + tb);
            }
            #pragma unroll
            for (int i = 0; i < 2; ++i) {
                const float ta = __shfl_xor_sync(0xffffffffu, v[i], 8);
                const float tb = __shfl_xor_sync(0xffffffffu, v[i + 2], 8);
                v[i] = ((lane & 8) == 0) ? (v[i] + ta) : (v[i + 2] + tb);
            }
            {
                const float ta = __shfl_xor_sync(0xffffffffu, v[0], 4);
                const float tb = __shfl_xor_sync(0xffffffffu, v[1], 4);
                v[0] = ((lane & 4) == 0) ? (v[0] + ta) : (v[1] + tb);
            }
            v[0] += __shfl_xor_sync(0xffffffffu, v[0], 2);
            v[0] += __shfl_xor_sync(0xffffffffu, v[0], 1);
            if ((lane & 3) == 0) s_u[p][(lane >> 2) * 16 + w] = v[0];
            __syncthreads();
            // threads grp*8..grp*8+7 own this group's rows (their r_pre)
            if ((t >> 3) == grp) {
                const int i = t & 7;
                float u = 0.f;
                #pragma unroll
                for (int w2 = 0; w2 < 16; ++w2) u += s_u[p][i * 16 + w2];
                const float rn = r_pre / fmaf(r_pre, u, EPS);
                g_r[b * N + rowg + i] = rn;   // fire-and-forget store
                r_s[p][i] = rn;
            }
        } else {
            if ((t >> 3) == grp) r_s[p][t & 7] = r_pre;
        }
        __syncthreads();

        // phase B: thread-local column sums over register-held rows
        #pragma unroll
        for (int i = 0; i < RPG; ++i) {
            const float ri = r_s[p][i];
            const float2 f0 = bf2f(e[i].x);
            const float2 f1 = bf2f(e[i].y);
            const float2 f2 = bf2f(e[i].z);
            const float2 f3 = bf2f(e[i].w);
            a0 = fmaf(f0.x, ri, a0); a1 = fmaf(f0.y, ri, a1);
            a2 = fmaf(f1.x, ri, a2); a3 = fmaf(f1.y, ri, a3);
            a4 = fmaf(f2.x, ri, a4); a5 = fmaf(f2.y, ri, a5);
            a6 = fmaf(f3.x, ri, a6); a7 = fmaf(f3.y, ri, a7);
        }
        // no trailing barrier needed: next group uses other parity buffers
    }

    // pack 8 fp32 partials -> 8 fp16, single STG.128 (evict_first: no pollute)
    __half2 h0 = __floats2half2_rn(a0, a1);
    __half2 h1 = __floats2half2_rn(a2, a3);
    __half2 h2 = __floats2half2_rn(a4, a5);
    __half2 h3 = __floats2half2_rn(a6, a7);
    uint4 pk;
    pk.x = *(unsigned*)&h0; pk.y = *(unsigned*)&h1;
    pk.z = *(unsigned*)&h2; pk.w = *(unsigned*)&h3;
    stg_pol4(((uint4*)(g_vpart + (size_t)bid * N)) + t, pk, polS);
}

// ---------------------------------------------------------------------------
// finalize: quad of threads per half2 column-pair; each sums 64 fp16 partials
// in fixed order (fp32 accum), fixed-order shfl combine; update 2 c values.
// ---------------------------------------------------------------------------
__global__ __launch_bounds__(256) void col_finalize() {
    const int tt   = threadIdx.x;
    const int pair = blockIdx.x * 64 + (tt >> 2);  // global half2 index, 0..8191
    const int q    = tt & 3;
    const int b    = pair >> 11;                   // 2048 half2 per batch
    const int jp   = pair & 2047;

    const __half2* vp = (const __half2*)g_vpart
                      + (size_t)(b * SPBATCH + q * 64) * (N / 2) + jp;
    float vx = 0.f, vy = 0.f;
    #pragma unroll 8
    for (int s = 0; s < 64; ++s) {
        const float2 f = __half22float2(vp[(size_t)s * (N / 2)]);
        vx += f.x; vy += f.y;
    }
    vx += __shfl_down_sync(0xffffffffu, vx, 1);
    vy += __shfl_down_sync(0xffffffffu, vy, 1);
    vx += __shfl_down_sync(0xffffffffu, vx, 2);
    vy += __shfl_down_sync(0xffffffffu, vy, 2);
    if (q == 0) {
        const int col = pair * 2;          // global (b*N + j)
        const float c0 = g_c[col];
        const float c1 = g_c[col + 1];
        g_c[col]     = c0 / fmaf(c0, vx, EPS);
        g_c[col + 1] = c1 / fmaf(c1, vy, EPS);
    }
}

// ---------------------------------------------------------------------------
// output: out_ij = exp(x_ij - rowmax_i) * r_i * c_j (fp32 path)
// ---------------------------------------------------------------------------
__global__ __launch_bounds__(256) void out_kernel(const float* __restrict__ logits,
                                                  float* __restrict__ out) {
    const size_t g  = (size_t)blockIdx.x * 256 + threadIdx.x;  // float4 index
    const size_t e0 = g * 4;
    const int row = (int)(e0 >> 12);
    const int b   = row >> 12;
    const int j   = (int)(e0 & (N - 1));

    const float mx = g_rowmax[row];
    const float r  = g_r[row];
    const float4 x = ((const float4*)logits)[g];
    const float4 c = *(const float4*)(g_c + b * N + j);

    float4 o;
    o.x = __expf(x.x - mx) * r * c.x;
    o.y = __expf(x.y - mx) * r * c.y;
    o.z = __expf(x.z - mx) * r * c.z;
    o.w = __expf(x.w - mx) * r * c.w;
    ((float4*)out)[g] = o;
}

extern "C" void kernel_launch(void* const* d_in, const int* in_sizes, int n_in,
                              void* d_out, int out_size) {
    const float* logits = (const float*)d_in[0];
    float* out = (float*)d_out;

    prep_kernel<<<RN, 256>>>(logits);          // includes row step #1
    for (int it = 0; it < NITER; ++it) {
        fused_kernel<<<GRID_F, 512>>>(it > 0); // it=0: col only (row folded)
        col_finalize<<<RN / 128, 256>>>();
    }
    out_kernel<<<(int)(((size_t)BATCH * N * N / 4) / 256), 256>>>(logits, out);
}